// round 2
// baseline (speedup 1.0000x reference)
#include <cuda_runtime.h>
#include <math.h>

#define KMAX   64
#define HASHN  256
#define MAXB   8
#define EMPTYK 0xFFFFFFFFu
#define LAMF   300.0f
#define CH     24      // k-chunk width for part B

// ---------------- device scratch (no allocations allowed) ----------------
__device__ unsigned int g_hash[MAXB * HASHN];       // per-batch global hash: color keys
__device__ float        g_scnt[MAXB * HASHN];       // per-slot pixel count
__device__ float        g_ssx [MAXB * HASHN];       // per-slot sum pred.x
__device__ float        g_ssy [MAXB * HASHN];
__device__ float        g_ssz [MAXB * HASHN];
__device__ unsigned int g_uniq[MAXB * KMAX];        // rank-sorted unique keys (EMPTY pad)
__device__ int          g_kreal[MAXB];
__device__ float        g_cnt [MAXB * KMAX];        // per-rank count
__device__ float4       g_h4  [MAXB * KMAX];        // (-2mx, -2my, -2mz, m2)
__device__ float4       g_mrw [MAXB * KMAX];        // (mx, my, mz, is_bg)
__device__ float        g_fsum[MAXB * KMAX];
__device__ float        g_own [MAXB * KMAX];
__device__ float        g_hub [MAXB * KMAX];

__device__ __forceinline__ float fast_rcp(float x) {
    float r;
    asm("rcp.approx.f32 %0, %1;" : "=f"(r) : "f"(x));
    return r;
}

__device__ __forceinline__ bool get_nobg(const void* p, int b) {
    const unsigned char* pb = (const unsigned char*)p;
    if (pb[0] == 0 && pb[1] == 0 && pb[2] == 0x80 && pb[3] == 0x3F) {
        const float* pf = (const float*)p;
        return pf[b] != 0.0f;
    }
    return pb[b] != 0;
}

__device__ __forceinline__ unsigned make_key(float r, float g, float bl) {
    return ((unsigned)r << 16) | ((unsigned)g << 8) | (unsigned)bl;
}

// ---------------- kernels ----------------
__global__ void k_init() {
    int i = blockIdx.x * blockDim.x + threadIdx.x;
    if (i < MAXB * HASHN) {
        g_hash[i] = EMPTYK;
        g_scnt[i] = 0.f; g_ssx[i] = 0.f; g_ssy[i] = 0.f; g_ssz[i] = 0.f;
    }
    if (i < MAXB * KMAX) {
        g_uniq[i] = EMPTYK;
        g_cnt[i] = 0.f; g_fsum[i] = 0.f; g_own[i] = 0.f; g_hub[i] = 0.f;
        g_h4[i]  = make_float4(0.f, 0.f, 0.f, 0.f);
        g_mrw[i] = make_float4(0.f, 0.f, 0.f, 0.f);
    }
    if (i < MAXB) g_kreal[i] = 0;
}

// Fused collect + per-segment accumulation. Per-block shared hash (coherent),
// one global merge of <=HASHN entries per block at the end.
__global__ void __launch_bounds__(256) k_collect(const float* __restrict__ pred,
                                                 const float* __restrict__ tgt, int P) {
    int b = blockIdx.y;
    __shared__ unsigned skey[HASHN];
    __shared__ float scnt[HASHN], ssx[HASHN], ssy[HASHN], ssz[HASHN];
    int tid = threadIdx.x;   // 256 == HASHN
    skey[tid] = EMPTYK;
    scnt[tid] = 0.f; ssx[tid] = 0.f; ssy[tid] = 0.f; ssz[tid] = 0.f;
    __syncthreads();

    const float* t  = tgt  + (size_t)b * 3 * P;
    const float* pr = pred + (size_t)b * 3 * P;
    int nvec = P >> 2;
    const float4* tx4 = (const float4*)(t);
    const float4* ty4 = (const float4*)(t + P);
    const float4* tz4 = (const float4*)(t + 2 * P);
    const float4* px4 = (const float4*)(pr);
    const float4* py4 = (const float4*)(pr + P);
    const float4* pz4 = (const float4*)(pr + 2 * P);
    int start  = blockIdx.x * blockDim.x + tid;
    int stride = gridDim.x * blockDim.x;

    for (int v = start; v < nvec; v += stride) {
        float4 r = tx4[v], g = ty4[v], bl = tz4[v];
        float4 x = px4[v], y = py4[v], z = pz4[v];
        unsigned keys[4] = { make_key(r.x, g.x, bl.x), make_key(r.y, g.y, bl.y),
                             make_key(r.z, g.z, bl.z), make_key(r.w, g.w, bl.w) };
        float pxs[4] = { x.x, x.y, x.z, x.w };
        float pys[4] = { y.x, y.y, y.z, y.w };
        float pzs[4] = { z.x, z.y, z.z, z.w };
        #pragma unroll
        for (int i = 0; i < 4; i++) {
            unsigned key = keys[i];
            unsigned slot = (key * 2654435761u) >> 24;
            #pragma unroll 1
            for (;;) {
                unsigned cur = *(volatile unsigned*)&skey[slot];
                if (cur == key) break;
                if (cur == EMPTYK) {
                    unsigned old = atomicCAS(&skey[slot], EMPTYK, key);
                    if (old == EMPTYK || old == key) break;
                }
                slot = (slot + 1) & (HASHN - 1);
            }
            atomicAdd(&scnt[slot], 1.0f);
            atomicAdd(&ssx[slot], pxs[i]);
            atomicAdd(&ssy[slot], pys[i]);
            atomicAdd(&ssz[slot], pzs[i]);
        }
    }
    // scalar tail (P % 4), handled by x-block 0 only
    if (blockIdx.x == 0) {
        for (int p = (nvec << 2) + tid; p < P; p += blockDim.x) {
            unsigned key = make_key(t[p], t[P + p], t[2 * P + p]);
            unsigned slot = (key * 2654435761u) >> 24;
            #pragma unroll 1
            for (;;) {
                unsigned cur = *(volatile unsigned*)&skey[slot];
                if (cur == key) break;
                if (cur == EMPTYK) {
                    unsigned old = atomicCAS(&skey[slot], EMPTYK, key);
                    if (old == EMPTYK || old == key) break;
                }
                slot = (slot + 1) & (HASHN - 1);
            }
            atomicAdd(&scnt[slot], 1.0f);
            atomicAdd(&ssx[slot], pr[p]);
            atomicAdd(&ssy[slot], pr[P + p]);
            atomicAdd(&ssz[slot], pr[2 * P + p]);
        }
    }
    __syncthreads();

    // merge: one thread per local slot probes the global table
    unsigned mk = skey[tid];
    if (mk != EMPTYK) {
        unsigned gs = (mk * 2654435761u) >> 24;
        #pragma unroll 1
        for (;;) {
            unsigned cur = __ldcg(&g_hash[b * HASHN + gs]);  // L2-fresh read
            if (cur == mk) break;
            if (cur == EMPTYK) {
                unsigned old = atomicCAS(&g_hash[b * HASHN + gs], EMPTYK, mk);
                if (old == EMPTYK || old == mk) break;
            }
            gs = (gs + 1) & (HASHN - 1);
        }
        atomicAdd(&g_scnt[b * HASHN + gs], scnt[tid]);
        atomicAdd(&g_ssx [b * HASHN + gs], ssx[tid]);
        atomicAdd(&g_ssy [b * HASHN + gs], ssy[tid]);
        atomicAdd(&g_ssz [b * HASHN + gs], ssz[tid]);
    }
}

// Fused sortuniq + means: rank keys, gather per-slot sums into rank order.
__global__ void k_rank() {
    int b = blockIdx.x;
    __shared__ unsigned keys[HASHN];
    __shared__ int scount;
    int tid = threadIdx.x;  // HASHN threads
    keys[tid] = g_hash[b * HASHN + tid];
    if (tid == 0) scount = 0;
    __syncthreads();
    unsigned mk = keys[tid];
    if (mk != EMPTYK) {
        int rank = 0;
        #pragma unroll 8
        for (int i = 0; i < HASHN; i++) rank += (keys[i] < mk) ? 1 : 0;
        atomicAdd(&scount, 1);
        if (rank < KMAX) {
            float c = g_scnt[b * HASHN + tid];
            float n = fmaxf(c, 1.0f);
            float inv = 1.0f / n;
            float mx = g_ssx[b * HASHN + tid] * inv;
            float my = g_ssy[b * HASHN + tid] * inv;
            float mz = g_ssz[b * HASHN + tid] * inv;
            float m2 = mx * mx + my * my + mz * mz;
            g_uniq[b * KMAX + rank] = mk;
            g_cnt [b * KMAX + rank] = c;
            g_h4  [b * KMAX + rank] = make_float4(-2.f * mx, -2.f * my, -2.f * mz, m2);
            g_mrw [b * KMAX + rank] = make_float4(mx, my, mz, (mk == 0u) ? 1.f : 0.f);
        }
    }
    __syncthreads();
    if (tid == 0) g_kreal[b] = min(scount, KMAX);
}

__device__ __forceinline__ int seg_search(const unsigned* us, unsigned key) {
    int pos = 0;
    #pragma unroll
    for (int st = 32; st >= 1; st >>= 1)
        if (us[pos + st] <= key) pos += st;
    return pos;
}

// part B chunk body: FULL=true -> compile-time 24-wide, no runtime predicate
template <bool FULL>
__device__ __forceinline__ void chunk_body(
    const float4* __restrict__ px4, const float4* __restrict__ py4,
    const float4* __restrict__ pz4, const float* __restrict__ pr, int P,
    const float4* h4s, float* fs_sh, int c0, int kl,
    int start, int stride, int nvec)
{
    float acc[CH];
    #pragma unroll
    for (int j = 0; j < CH; j++) acc[j] = 0.f;

    for (int v = start; v < nvec; v += stride) {
        float4 x = px4[v], y = py4[v], z = pz4[v];
        float cw0 = fmaf(x.x, x.x, fmaf(y.x, y.x, fmaf(z.x, z.x, 1.0f)));
        float cw1 = fmaf(x.y, x.y, fmaf(y.y, y.y, fmaf(z.y, z.y, 1.0f)));
        float cw2 = fmaf(x.z, x.z, fmaf(y.z, y.z, fmaf(z.z, z.z, 1.0f)));
        float cw3 = fmaf(x.w, x.w, fmaf(y.w, y.w, fmaf(z.w, z.w, 1.0f)));
        #pragma unroll
        for (int j = 0; j < CH; j++) {
            if (FULL || j < kl) {
                float4 h = h4s[c0 + j];
                float t0 = fmaf(x.x, h.x, cw0 + h.w);
                float t1 = fmaf(x.y, h.x, cw1 + h.w);
                float t2 = fmaf(x.z, h.x, cw2 + h.w);
                float t3 = fmaf(x.w, h.x, cw3 + h.w);
                t0 = fmaf(y.x, h.y, t0); t1 = fmaf(y.y, h.y, t1);
                t2 = fmaf(y.z, h.y, t2); t3 = fmaf(y.w, h.y, t3);
                t0 = fmaf(z.x, h.z, t0); t1 = fmaf(z.y, h.z, t1);
                t2 = fmaf(z.z, h.z, t2); t3 = fmaf(z.w, h.z, t3);
                float r0 = fast_rcp(fmaxf(t0, 1.0f));
                float r1 = fast_rcp(fmaxf(t1, 1.0f));
                float r2 = fast_rcp(fmaxf(t2, 1.0f));
                float r3 = fast_rcp(fmaxf(t3, 1.0f));
                acc[j] += (r0 + r1) + (r2 + r3);
            }
        }
    }
    // scalar tail
    for (int p = (nvec << 2) + start; p < P; p += stride) {
        float px = pr[p], py = pr[P + p], pz = pr[2 * P + p];
        float cw = fmaf(px, px, fmaf(py, py, fmaf(pz, pz, 1.0f)));
        #pragma unroll
        for (int j = 0; j < CH; j++) {
            if (FULL || j < kl) {
                float4 h = h4s[c0 + j];
                float tt = fmaf(px, h.x, cw + h.w);
                tt = fmaf(py, h.y, tt);
                tt = fmaf(pz, h.z, tt);
                acc[j] += fast_rcp(fmaxf(tt, 1.0f));
            }
        }
    }
    #pragma unroll
    for (int j = 0; j < CH; j++)
        if (FULL || j < kl) atomicAdd(&fs_sh[c0 + j], acc[j]);
}

__global__ void __launch_bounds__(256) k_pass2(const float* __restrict__ pred,
                                               const float* __restrict__ tgt, int P) {
    int b = blockIdx.y;
    __shared__ unsigned us[KMAX];
    __shared__ float4 h4s[KMAX];
    __shared__ float4 ms[KMAX];
    __shared__ float hub_sh[KMAX], own_sh[KMAX], fs_sh[KMAX];
    int tid = threadIdx.x;
    if (tid < KMAX) {
        us[tid]  = g_uniq[b * KMAX + tid];
        h4s[tid] = g_h4[b * KMAX + tid];
        ms[tid]  = g_mrw[b * KMAX + tid];
        hub_sh[tid] = 0.f; own_sh[tid] = 0.f; fs_sh[tid] = 0.f;
    }
    __syncthreads();
    int Kr = g_kreal[b];
    const float* t  = tgt  + (size_t)b * 3 * P;
    const float* pr = pred + (size_t)b * 3 * P;
    int nvec = P >> 2;
    const float4* tx4 = (const float4*)(t);
    const float4* ty4 = (const float4*)(t + P);
    const float4* tz4 = (const float4*)(t + 2 * P);
    const float4* px4 = (const float4*)(pr);
    const float4* py4 = (const float4*)(pr + P);
    const float4* pz4 = (const float4*)(pr + 2 * P);
    int start  = blockIdx.x * blockDim.x + tid;
    int stride = gridDim.x * blockDim.x;

    // ---- Part A: segment id, huber, own-f (4 px / iter) ----
    for (int v = start; v < nvec; v += stride) {
        float4 r = tx4[v], g = ty4[v], bl = tz4[v];
        float4 x = px4[v], y = py4[v], z = pz4[v];
        unsigned keys[4] = { make_key(r.x, g.x, bl.x), make_key(r.y, g.y, bl.y),
                             make_key(r.z, g.z, bl.z), make_key(r.w, g.w, bl.w) };
        float pxs[4] = { x.x, x.y, x.z, x.w };
        float pys[4] = { y.x, y.y, y.z, y.w };
        float pzs[4] = { z.x, z.y, z.z, z.w };
        #pragma unroll
        for (int i = 0; i < 4; i++) {
            int pos = seg_search(us, keys[i]);
            float4 m = ms[pos];
            float dx = pxs[i] - m.x, dy = pys[i] - m.y, dz = pzs[i] - m.z;
            float d = fmaf(dx, dx, fmaf(dy, dy, dz * dz));
            atomicAdd(&own_sh[pos], fast_rcp(1.0f + d));
            bool bg = (m.w != 0.f);
            float ex = bg ? pxs[i] : dx;
            float ey = bg ? pys[i] : dy;
            float ez = bg ? pzs[i] : dz;
            float h = 0.f, a;
            a = fabsf(ex); h += (a < 1.f) ? 0.5f * ex * ex : a - 0.5f;
            a = fabsf(ey); h += (a < 1.f) ? 0.5f * ey * ey : a - 0.5f;
            a = fabsf(ez); h += (a < 1.f) ? 0.5f * ez * ez : a - 0.5f;
            atomicAdd(&hub_sh[pos], h);
        }
    }
    if (blockIdx.x == 0) {   // scalar tail
        for (int p = (nvec << 2) + tid; p < P; p += blockDim.x) {
            float px = pr[p], py = pr[P + p], pz = pr[2 * P + p];
            unsigned key = make_key(t[p], t[P + p], t[2 * P + p]);
            int pos = seg_search(us, key);
            float4 m = ms[pos];
            float dx = px - m.x, dy = py - m.y, dz = pz - m.z;
            float d = fmaf(dx, dx, fmaf(dy, dy, dz * dz));
            atomicAdd(&own_sh[pos], fast_rcp(1.0f + d));
            bool bg = (m.w != 0.f);
            float ex = bg ? px : dx, ey = bg ? py : dy, ez = bg ? pz : dz;
            float h = 0.f, a;
            a = fabsf(ex); h += (a < 1.f) ? 0.5f * ex * ex : a - 0.5f;
            a = fabsf(ey); h += (a < 1.f) ? 0.5f * ey * ey : a - 0.5f;
            a = fabsf(ez); h += (a < 1.f) ? 0.5f * ez * ez : a - 0.5f;
            atomicAdd(&hub_sh[pos], h);
        }
    }

    // ---- Part B: dense f-sum over k ----
    int nfull = (Kr / CH) * CH;
    for (int c0 = 0; c0 < nfull; c0 += CH)
        chunk_body<true>(px4, py4, pz4, pr, P, h4s, fs_sh, c0, CH, start, stride, nvec);
    if (nfull < Kr)
        chunk_body<false>(px4, py4, pz4, pr, P, h4s, fs_sh, nfull, Kr - nfull, start, stride, nvec);

    __syncthreads();
    if (tid < KMAX) {
        if (hub_sh[tid] != 0.f) atomicAdd(&g_hub [b * KMAX + tid], hub_sh[tid]);
        if (own_sh[tid] != 0.f) atomicAdd(&g_own [b * KMAX + tid], own_sh[tid]);
        if (fs_sh[tid]  != 0.f) atomicAdd(&g_fsum[b * KMAX + tid], fs_sh[tid]);
    }
}

__global__ void k_final(float* out, const void* nbg_raw, int B, int P) {
    int tid = threadIdx.x;           // B * KMAX threads
    int b = tid / KMAX, k = tid % KMAX;
    __shared__ float s_ct[MAXB], s_hub[MAXB], s_sep[MAXB], s_pair[MAXB];
    __shared__ float4 me_sh[MAXB * KMAX];
    __shared__ unsigned char cnted_sh[MAXB * KMAX];
    if (tid < MAXB) { s_ct[tid] = 0.f; s_hub[tid] = 0.f; s_sep[tid] = 0.f; s_pair[tid] = 0.f; }
    __syncthreads();

    bool counted = false;
    float4 me = make_float4(0.f, 0.f, 0.f, 0.f);
    if (b < B) {
        bool nb = get_nobg(nbg_raw, b);
        float c = g_cnt[b * KMAX + k];
        bool valid = (c > 0.f);
        float4 m = g_mrw[b * KMAX + k];
        bool isbg = (m.w != 0.f);
        counted = valid && (!isbg || !nb);
        if (!isbg) me = m;
        float n = fmaxf(c, 1.0f);
        if (counted) {
            atomicAdd(&s_ct[b], 1.f);
            atomicAdd(&s_hub[b], g_hub[b * KMAX + k] / (3.0f * n));
        }
        float n_out = (float)P - c;
        if (valid && !isbg && n_out > 0.f) {
            float sep_mean = LAMF * (g_fsum[b * KMAX + k] - g_own[b * KMAX + k]) / fmaxf(n_out, 1.0f);
            atomicAdd(&s_sep[b], (10.0f / sqrtf(n)) * sep_mean);
        }
    }
    me_sh[tid] = me;
    cnted_sh[tid] = counted ? 1 : 0;
    __syncthreads();

    if (b < B && counted) {
        float psum = 0.f;
        for (int k2 = 0; k2 < KMAX; k2++) {
            if (k2 == k || !cnted_sh[b * KMAX + k2]) continue;
            float4 o = me_sh[b * KMAX + k2];
            float dx = me.x - o.x, dy = me.y - o.y, dz = me.z - o.z;
            float sq = dx * dx + dy * dy + dz * dz;
            psum += LAMF / (sq + 1.0f);
        }
        atomicAdd(&s_pair[b], psum);
    }
    __syncthreads();
    if (tid == 0) {
        float tot = 0.f;
        for (int bb = 0; bb < B; bb++) {
            float ct = s_ct[bb];
            float pair_sum = s_pair[bb] * 0.5f;
            float n_pairs = ct * (ct - 1.0f) * 0.5f;
            float mean_sep = (ct > 1.0f) ? pair_sum / fmaxf(n_pairs, 1.0f) : 0.f;
            float loss = s_hub[bb] + s_sep[bb] + mean_sep;
            tot += loss / fmaxf(ct, 1.0f);
        }
        out[0] = tot / (float)B;
    }
}

// ---------------- launch ----------------
extern "C" void kernel_launch(void* const* d_in, const int* in_sizes, int n_in,
                              void* d_out, int out_size) {
    const float* pred = (const float*)d_in[0];
    const float* tgt  = (const float*)d_in[1];
    const void*  nbg  = d_in[2];
    int B = in_sizes[2];
    if (B > MAXB) B = MAXB;
    int P = in_sizes[0] / (3 * B);

    k_init<<<16, 256>>>();
    k_collect<<<dim3(256, B), 256>>>(pred, tgt, P);
    k_rank<<<B, HASHN>>>();
    k_pass2<<<dim3(296, B), 256>>>(pred, tgt, P);
    k_final<<<1, B * KMAX>>>((float*)d_out, nbg, B, P);
}

// round 3
// speedup vs baseline: 1.5808x; 1.5808x over previous
#include <cuda_runtime.h>
#include <math.h>

#define KMAX   64
#define HASHN  256
#define MAXB   8
#define EMPTYK 0xFFFFFFFFu
#define LAMF   300.0f
#define CH     8       // k-chunk width for part B (register-hoisted)

// ---------------- device scratch (no allocations allowed) ----------------
__device__ unsigned int g_hash[MAXB * HASHN];
__device__ float        g_scnt[MAXB * HASHN];
__device__ float        g_ssx [MAXB * HASHN];
__device__ float        g_ssy [MAXB * HASHN];
__device__ float        g_ssz [MAXB * HASHN];
__device__ unsigned int g_uniq[MAXB * KMAX];
__device__ int          g_kreal[MAXB];
__device__ float        g_cnt [MAXB * KMAX];
__device__ float4       g_h4  [MAXB * KMAX];   // (-2mx, -2my, -2mz, m2)
__device__ float4       g_mrw [MAXB * KMAX];   // (mx, my, mz, is_bg)
__device__ float        g_fsum[MAXB * KMAX];
__device__ float        g_own [MAXB * KMAX];
__device__ float        g_hub [MAXB * KMAX];

__device__ __forceinline__ float fast_rcp(float x) {
    float r;
    asm("rcp.approx.f32 %0, %1;" : "=f"(r) : "f"(x));
    return r;
}

__device__ __forceinline__ bool get_nobg(const void* p, int b) {
    const unsigned char* pb = (const unsigned char*)p;
    if (pb[0] == 0 && pb[1] == 0 && pb[2] == 0x80 && pb[3] == 0x3F) {
        const float* pf = (const float*)p;
        return pf[b] != 0.0f;
    }
    return pb[b] != 0;
}

__device__ __forceinline__ unsigned make_key(float r, float g, float bl) {
    return ((unsigned)r << 16) | ((unsigned)g << 8) | (unsigned)bl;
}

// ---------------- kernels ----------------
__global__ void k_init() {
    int i = blockIdx.x * blockDim.x + threadIdx.x;
    if (i < MAXB * HASHN) {
        g_hash[i] = EMPTYK;
        g_scnt[i] = 0.f; g_ssx[i] = 0.f; g_ssy[i] = 0.f; g_ssz[i] = 0.f;
    }
    if (i < MAXB * KMAX) {
        g_uniq[i] = EMPTYK;
        g_cnt[i] = 0.f; g_fsum[i] = 0.f; g_own[i] = 0.f; g_hub[i] = 0.f;
        g_h4[i]  = make_float4(0.f, 0.f, 0.f, 0.f);
        g_mrw[i] = make_float4(0.f, 0.f, 0.f, 0.f);
    }
    if (i < MAXB) g_kreal[i] = 0;
}

// Fused collect + per-segment accumulation, per-block shared hash.
__global__ void __launch_bounds__(256) k_collect(const float* __restrict__ pred,
                                                 const float* __restrict__ tgt, int P) {
    int b = blockIdx.y;
    __shared__ unsigned skey[HASHN];
    __shared__ float scnt[HASHN], ssx[HASHN], ssy[HASHN], ssz[HASHN];
    int tid = threadIdx.x;
    skey[tid] = EMPTYK;
    scnt[tid] = 0.f; ssx[tid] = 0.f; ssy[tid] = 0.f; ssz[tid] = 0.f;
    __syncthreads();

    const float* t  = tgt  + (size_t)b * 3 * P;
    const float* pr = pred + (size_t)b * 3 * P;
    int nvec = P >> 2;
    const float4* tx4 = (const float4*)(t);
    const float4* ty4 = (const float4*)(t + P);
    const float4* tz4 = (const float4*)(t + 2 * P);
    const float4* px4 = (const float4*)(pr);
    const float4* py4 = (const float4*)(pr + P);
    const float4* pz4 = (const float4*)(pr + 2 * P);
    int start  = blockIdx.x * blockDim.x + tid;
    int stride = gridDim.x * blockDim.x;

    for (int v = start; v < nvec; v += stride) {
        float4 r = tx4[v], g = ty4[v], bl = tz4[v];
        float4 x = px4[v], y = py4[v], z = pz4[v];
        unsigned keys[4] = { make_key(r.x, g.x, bl.x), make_key(r.y, g.y, bl.y),
                             make_key(r.z, g.z, bl.z), make_key(r.w, g.w, bl.w) };
        float pxs[4] = { x.x, x.y, x.z, x.w };
        float pys[4] = { y.x, y.y, y.z, y.w };
        float pzs[4] = { z.x, z.y, z.z, z.w };
        #pragma unroll
        for (int i = 0; i < 4; i++) {
            unsigned key = keys[i];
            unsigned slot = (key * 2654435761u) >> 24;
            #pragma unroll 1
            for (;;) {
                unsigned cur = *(volatile unsigned*)&skey[slot];
                if (cur == key) break;
                if (cur == EMPTYK) {
                    unsigned old = atomicCAS(&skey[slot], EMPTYK, key);
                    if (old == EMPTYK || old == key) break;
                }
                slot = (slot + 1) & (HASHN - 1);
            }
            atomicAdd(&scnt[slot], 1.0f);
            atomicAdd(&ssx[slot], pxs[i]);
            atomicAdd(&ssy[slot], pys[i]);
            atomicAdd(&ssz[slot], pzs[i]);
        }
    }
    if (blockIdx.x == 0) {  // scalar tail
        for (int p = (nvec << 2) + tid; p < P; p += blockDim.x) {
            unsigned key = make_key(t[p], t[P + p], t[2 * P + p]);
            unsigned slot = (key * 2654435761u) >> 24;
            #pragma unroll 1
            for (;;) {
                unsigned cur = *(volatile unsigned*)&skey[slot];
                if (cur == key) break;
                if (cur == EMPTYK) {
                    unsigned old = atomicCAS(&skey[slot], EMPTYK, key);
                    if (old == EMPTYK || old == key) break;
                }
                slot = (slot + 1) & (HASHN - 1);
            }
            atomicAdd(&scnt[slot], 1.0f);
            atomicAdd(&ssx[slot], pr[p]);
            atomicAdd(&ssy[slot], pr[P + p]);
            atomicAdd(&ssz[slot], pr[2 * P + p]);
        }
    }
    __syncthreads();

    unsigned mk = skey[tid];
    if (mk != EMPTYK) {
        unsigned gs = (mk * 2654435761u) >> 24;
        #pragma unroll 1
        for (;;) {
            unsigned cur = __ldcg(&g_hash[b * HASHN + gs]);
            if (cur == mk) break;
            if (cur == EMPTYK) {
                unsigned old = atomicCAS(&g_hash[b * HASHN + gs], EMPTYK, mk);
                if (old == EMPTYK || old == mk) break;
            }
            gs = (gs + 1) & (HASHN - 1);
        }
        atomicAdd(&g_scnt[b * HASHN + gs], scnt[tid]);
        atomicAdd(&g_ssx [b * HASHN + gs], ssx[tid]);
        atomicAdd(&g_ssy [b * HASHN + gs], ssy[tid]);
        atomicAdd(&g_ssz [b * HASHN + gs], ssz[tid]);
    }
}

// Rank unique keys and produce means / h4 tables in rank order.
__global__ void k_rank() {
    int b = blockIdx.x;
    __shared__ unsigned keys[HASHN];
    __shared__ int scount;
    int tid = threadIdx.x;
    keys[tid] = g_hash[b * HASHN + tid];
    if (tid == 0) scount = 0;
    __syncthreads();
    unsigned mk = keys[tid];
    if (mk != EMPTYK) {
        int rank = 0;
        #pragma unroll 8
        for (int i = 0; i < HASHN; i++) rank += (keys[i] < mk) ? 1 : 0;
        atomicAdd(&scount, 1);
        if (rank < KMAX) {
            float c = g_scnt[b * HASHN + tid];
            float n = fmaxf(c, 1.0f);
            float inv = 1.0f / n;
            float mx = g_ssx[b * HASHN + tid] * inv;
            float my = g_ssy[b * HASHN + tid] * inv;
            float mz = g_ssz[b * HASHN + tid] * inv;
            float m2 = mx * mx + my * my + mz * mz;
            g_uniq[b * KMAX + rank] = mk;
            g_cnt [b * KMAX + rank] = c;
            g_h4  [b * KMAX + rank] = make_float4(-2.f * mx, -2.f * my, -2.f * mz, m2);
            g_mrw [b * KMAX + rank] = make_float4(mx, my, mz, (mk == 0u) ? 1.f : 0.f);
        }
    }
    __syncthreads();
    if (tid == 0) g_kreal[b] = min(scount, KMAX);
}

__device__ __forceinline__ int seg_search(const unsigned* us, unsigned key) {
    int pos = 0;
    #pragma unroll
    for (int st = 32; st >= 1; st >>= 1)
        if (us[pos + st] <= key) pos += st;
    return pos;
}

// Part B chunk body. h4 values are HOISTED INTO REGISTERS before the pixel
// loop (local array, static indexing, fully unrolled) so the hot loop has
// no LDS and no runtime predicates. Padding entries use a huge m2; their
// accumulators are discarded at merge.
__device__ __forceinline__ void chunk_body(
    const float4* __restrict__ px4, const float4* __restrict__ py4,
    const float4* __restrict__ pz4, const float* __restrict__ pr, int P,
    const float4* h4s, float* fs_sh, int c0, int kl,
    int start, int stride, int nvec)
{
    float4 h[CH];
    #pragma unroll
    for (int j = 0; j < CH; j++)
        h[j] = (j < kl) ? h4s[c0 + j] : make_float4(0.f, 0.f, 0.f, 3.0e8f);
    float acc[CH];
    #pragma unroll
    for (int j = 0; j < CH; j++) acc[j] = 0.f;

    for (int v = start; v < nvec; v += stride) {
        float4 x = px4[v], y = py4[v], z = pz4[v];
        float cw0 = fmaf(x.x, x.x, fmaf(y.x, y.x, fmaf(z.x, z.x, 1.0f)));
        float cw1 = fmaf(x.y, x.y, fmaf(y.y, y.y, fmaf(z.y, z.y, 1.0f)));
        float cw2 = fmaf(x.z, x.z, fmaf(y.z, y.z, fmaf(z.z, z.z, 1.0f)));
        float cw3 = fmaf(x.w, x.w, fmaf(y.w, y.w, fmaf(z.w, z.w, 1.0f)));
        #pragma unroll
        for (int j = 0; j < CH; j++) {
            float t0 = fmaf(x.x, h[j].x, cw0 + h[j].w);
            float t1 = fmaf(x.y, h[j].x, cw1 + h[j].w);
            float t2 = fmaf(x.z, h[j].x, cw2 + h[j].w);
            float t3 = fmaf(x.w, h[j].x, cw3 + h[j].w);
            t0 = fmaf(y.x, h[j].y, t0); t1 = fmaf(y.y, h[j].y, t1);
            t2 = fmaf(y.z, h[j].y, t2); t3 = fmaf(y.w, h[j].y, t3);
            t0 = fmaf(z.x, h[j].z, t0); t1 = fmaf(z.y, h[j].z, t1);
            t2 = fmaf(z.z, h[j].z, t2); t3 = fmaf(z.w, h[j].z, t3);
            float r0 = fast_rcp(fmaxf(t0, 1.0f));
            float r1 = fast_rcp(fmaxf(t1, 1.0f));
            float r2 = fast_rcp(fmaxf(t2, 1.0f));
            float r3 = fast_rcp(fmaxf(t3, 1.0f));
            acc[j] += (r0 + r1) + (r2 + r3);
        }
    }
    // scalar tail
    for (int p = (nvec << 2) + start; p < P; p += stride) {
        float px = pr[p], py = pr[P + p], pz = pr[2 * P + p];
        float cw = fmaf(px, px, fmaf(py, py, fmaf(pz, pz, 1.0f)));
        #pragma unroll
        for (int j = 0; j < CH; j++) {
            float tt = fmaf(px, h[j].x, cw + h[j].w);
            tt = fmaf(py, h[j].y, tt);
            tt = fmaf(pz, h[j].z, tt);
            acc[j] += fast_rcp(fmaxf(tt, 1.0f));
        }
    }
    #pragma unroll
    for (int j = 0; j < CH; j++)
        if (j < kl) atomicAdd(&fs_sh[c0 + j], acc[j]);
}

__global__ void __launch_bounds__(256) k_pass2(const float* __restrict__ pred,
                                               const float* __restrict__ tgt, int P) {
    int b = blockIdx.y;
    __shared__ unsigned us[KMAX];
    __shared__ float4 ms[KMAX];
    __shared__ float hub_sh[KMAX], own_sh[KMAX], fs_sh[KMAX];
    int tid = threadIdx.x;
    if (tid < KMAX) {
        us[tid]  = g_uniq[b * KMAX + tid];
        ms[tid]  = g_mrw[b * KMAX + tid];
        hub_sh[tid] = 0.f; own_sh[tid] = 0.f; fs_sh[tid] = 0.f;
    }
    __syncthreads();
    int Kr = g_kreal[b];
    const float* t  = tgt  + (size_t)b * 3 * P;
    const float* pr = pred + (size_t)b * 3 * P;
    int nvec = P >> 2;
    const float4* tx4 = (const float4*)(t);
    const float4* ty4 = (const float4*)(t + P);
    const float4* tz4 = (const float4*)(t + 2 * P);
    const float4* px4 = (const float4*)(pr);
    const float4* py4 = (const float4*)(pr + P);
    const float4* pz4 = (const float4*)(pr + 2 * P);
    int start  = blockIdx.x * blockDim.x + tid;
    int stride = gridDim.x * blockDim.x;

    // ---- Part A: segment id, huber, own-f ----
    for (int v = start; v < nvec; v += stride) {
        float4 r = tx4[v], g = ty4[v], bl = tz4[v];
        float4 x = px4[v], y = py4[v], z = pz4[v];
        unsigned keys[4] = { make_key(r.x, g.x, bl.x), make_key(r.y, g.y, bl.y),
                             make_key(r.z, g.z, bl.z), make_key(r.w, g.w, bl.w) };
        float pxs[4] = { x.x, x.y, x.z, x.w };
        float pys[4] = { y.x, y.y, y.z, y.w };
        float pzs[4] = { z.x, z.y, z.z, z.w };
        #pragma unroll
        for (int i = 0; i < 4; i++) {
            int pos = seg_search(us, keys[i]);
            float4 m = ms[pos];
            float dx = pxs[i] - m.x, dy = pys[i] - m.y, dz = pzs[i] - m.z;
            float d = fmaf(dx, dx, fmaf(dy, dy, dz * dz));
            atomicAdd(&own_sh[pos], fast_rcp(1.0f + d));
            bool bg = (m.w != 0.f);
            float ex = bg ? pxs[i] : dx;
            float ey = bg ? pys[i] : dy;
            float ez = bg ? pzs[i] : dz;
            float hh = 0.f, a;
            a = fabsf(ex); hh += (a < 1.f) ? 0.5f * ex * ex : a - 0.5f;
            a = fabsf(ey); hh += (a < 1.f) ? 0.5f * ey * ey : a - 0.5f;
            a = fabsf(ez); hh += (a < 1.f) ? 0.5f * ez * ez : a - 0.5f;
            atomicAdd(&hub_sh[pos], hh);
        }
    }
    if (blockIdx.x == 0) {  // scalar tail
        for (int p = (nvec << 2) + tid; p < P; p += blockDim.x) {
            float px = pr[p], py = pr[P + p], pz = pr[2 * P + p];
            unsigned key = make_key(t[p], t[P + p], t[2 * P + p]);
            int pos = seg_search(us, key);
            float4 m = ms[pos];
            float dx = px - m.x, dy = py - m.y, dz = pz - m.z;
            float d = fmaf(dx, dx, fmaf(dy, dy, dz * dz));
            atomicAdd(&own_sh[pos], fast_rcp(1.0f + d));
            bool bg = (m.w != 0.f);
            float ex = bg ? px : dx, ey = bg ? py : dy, ez = bg ? pz : dz;
            float hh = 0.f, a;
            a = fabsf(ex); hh += (a < 1.f) ? 0.5f * ex * ex : a - 0.5f;
            a = fabsf(ey); hh += (a < 1.f) ? 0.5f * ey * ey : a - 0.5f;
            a = fabsf(ez); hh += (a < 1.f) ? 0.5f * ez * ez : a - 0.5f;
            atomicAdd(&hub_sh[pos], hh);
        }
    }

    // ---- Part B: dense f-sum over k (register-hoisted chunks of CH) ----
    const float4* h4g = &g_h4[b * KMAX];   // read via L1/L2, tiny
    for (int c0 = 0; c0 < Kr; c0 += CH) {
        int kl = min(CH, Kr - c0);
        chunk_body(px4, py4, pz4, pr, P, h4g, fs_sh, c0, kl, start, stride, nvec);
    }

    __syncthreads();
    if (tid < KMAX) {
        if (hub_sh[tid] != 0.f) atomicAdd(&g_hub [b * KMAX + tid], hub_sh[tid]);
        if (own_sh[tid] != 0.f) atomicAdd(&g_own [b * KMAX + tid], own_sh[tid]);
        if (fs_sh[tid]  != 0.f) atomicAdd(&g_fsum[b * KMAX + tid], fs_sh[tid]);
    }
}

__global__ void k_final(float* out, const void* nbg_raw, int B, int P) {
    int tid = threadIdx.x;           // B * KMAX threads
    int b = tid / KMAX, k = tid % KMAX;
    __shared__ float s_ct[MAXB], s_hub[MAXB], s_sep[MAXB], s_pair[MAXB];
    __shared__ float4 me_sh[MAXB * KMAX];
    __shared__ unsigned char cnted_sh[MAXB * KMAX];
    if (tid < MAXB) { s_ct[tid] = 0.f; s_hub[tid] = 0.f; s_sep[tid] = 0.f; s_pair[tid] = 0.f; }
    __syncthreads();

    bool counted = false;
    float4 me = make_float4(0.f, 0.f, 0.f, 0.f);
    if (b < B) {
        bool nb = get_nobg(nbg_raw, b);
        float c = g_cnt[b * KMAX + k];
        bool valid = (c > 0.f);
        float4 m = g_mrw[b * KMAX + k];
        bool isbg = (m.w != 0.f);
        counted = valid && (!isbg || !nb);
        if (!isbg) me = m;
        float n = fmaxf(c, 1.0f);
        if (counted) {
            atomicAdd(&s_ct[b], 1.f);
            atomicAdd(&s_hub[b], g_hub[b * KMAX + k] / (3.0f * n));
        }
        float n_out = (float)P - c;
        if (valid && !isbg && n_out > 0.f) {
            float sep_mean = LAMF * (g_fsum[b * KMAX + k] - g_own[b * KMAX + k]) / fmaxf(n_out, 1.0f);
            atomicAdd(&s_sep[b], (10.0f / sqrtf(n)) * sep_mean);
        }
    }
    me_sh[tid] = me;
    cnted_sh[tid] = counted ? 1 : 0;
    __syncthreads();

    if (b < B && counted) {
        float psum = 0.f;
        for (int k2 = 0; k2 < KMAX; k2++) {
            if (k2 == k || !cnted_sh[b * KMAX + k2]) continue;
            float4 o = me_sh[b * KMAX + k2];
            float dx = me.x - o.x, dy = me.y - o.y, dz = me.z - o.z;
            float sq = dx * dx + dy * dy + dz * dz;
            psum += LAMF / (sq + 1.0f);
        }
        atomicAdd(&s_pair[b], psum);
    }
    __syncthreads();
    if (tid == 0) {
        float tot = 0.f;
        for (int bb = 0; bb < B; bb++) {
            float ct = s_ct[bb];
            float pair_sum = s_pair[bb] * 0.5f;
            float n_pairs = ct * (ct - 1.0f) * 0.5f;
            float mean_sep = (ct > 1.0f) ? pair_sum / fmaxf(n_pairs, 1.0f) : 0.f;
            float loss = s_hub[bb] + s_sep[bb] + mean_sep;
            tot += loss / fmaxf(ct, 1.0f);
        }
        out[0] = tot / (float)B;
    }
}

// ---------------- launch ----------------
extern "C" void kernel_launch(void* const* d_in, const int* in_sizes, int n_in,
                              void* d_out, int out_size) {
    const float* pred = (const float*)d_in[0];
    const float* tgt  = (const float*)d_in[1];
    const void*  nbg  = d_in[2];
    int B = in_sizes[2];
    if (B > MAXB) B = MAXB;
    int P = in_sizes[0] / (3 * B);

    k_init<<<16, 256>>>();
    k_collect<<<dim3(256, B), 256>>>(pred, tgt, P);
    k_rank<<<B, HASHN>>>();
    k_pass2<<<dim3(296, B), 256>>>(pred, tgt, P);
    k_final<<<1, B * KMAX>>>((float*)d_out, nbg, B, P);
}

// round 4
// speedup vs baseline: 8.4357x; 5.3362x over previous
#include <cuda_runtime.h>
#include <math.h>

#define KMAX   64
#define HASHN  256
#define MAXB   8
#define EMPTYK 0xFFFFFFFFu
#define LAMF   300.0f
#define CH     8       // k-chunk width (one grid.z slice per chunk)
#define NCHUNK (KMAX / CH)

// ---------------- device scratch (no allocations allowed) ----------------
__device__ unsigned int g_hash[MAXB * HASHN];
__device__ float        g_scnt[MAXB * HASHN];
__device__ float        g_ssx [MAXB * HASHN];
__device__ float        g_ssy [MAXB * HASHN];
__device__ float        g_ssz [MAXB * HASHN];
__device__ unsigned int g_uniq[MAXB * KMAX];
__device__ int          g_kreal[MAXB];
__device__ float        g_cnt [MAXB * KMAX];
__device__ float4       g_h4  [MAXB * KMAX];   // (-2mx, -2my, -2mz, m2 + 1)
__device__ float4       g_mrw [MAXB * KMAX];   // (mx, my, mz, is_bg)
__device__ float        g_fsum[MAXB * KMAX];
__device__ float        g_own [MAXB * KMAX];
__device__ float        g_hub [MAXB * KMAX];

typedef unsigned long long ull;

__device__ __forceinline__ float fast_rcp(float x) {
    float r;
    asm("rcp.approx.f32 %0, %1;" : "=f"(r) : "f"(x));
    return r;
}
// packed f32x2 helpers (Blackwell)
__device__ __forceinline__ ull pk2(float lo, float hi) {
    ull r; asm("mov.b64 %0, {%1, %2};" : "=l"(r) : "f"(lo), "f"(hi)); return r;
}
__device__ __forceinline__ void upk2(ull v, float& lo, float& hi) {
    asm("mov.b64 {%0, %1}, %2;" : "=f"(lo), "=f"(hi) : "l"(v));
}
__device__ __forceinline__ ull fma2_(ull a, ull b, ull c) {
    ull d; asm("fma.rn.f32x2 %0, %1, %2, %3;" : "=l"(d) : "l"(a), "l"(b), "l"(c)); return d;
}
__device__ __forceinline__ ull add2_(ull a, ull b) {
    ull d; asm("add.rn.f32x2 %0, %1, %2;" : "=l"(d) : "l"(a), "l"(b)); return d;
}
__device__ __forceinline__ ull mul2_(ull a, ull b) {
    ull d; asm("mul.rn.f32x2 %0, %1, %2;" : "=l"(d) : "l"(a), "l"(b)); return d;
}
// magic-constant approximate reciprocal (alu pipe, no MUFU); |rel err| <= ~5%
__device__ __forceinline__ float magic_rcp(float x) {
    return __int_as_float(0x7EF311C3 - __float_as_int(x));
}

__device__ __forceinline__ bool get_nobg(const void* p, int b) {
    const unsigned char* pb = (const unsigned char*)p;
    if (pb[0] == 0 && pb[1] == 0 && pb[2] == 0x80 && pb[3] == 0x3F) {
        const float* pf = (const float*)p;
        return pf[b] != 0.0f;
    }
    return pb[b] != 0;
}
__device__ __forceinline__ unsigned make_key(float r, float g, float bl) {
    return ((unsigned)r << 16) | ((unsigned)g << 8) | (unsigned)bl;
}

// ---------------- kernels ----------------
__global__ void k_init() {
    int i = blockIdx.x * blockDim.x + threadIdx.x;
    if (i < MAXB * HASHN) {
        g_hash[i] = EMPTYK;
        g_scnt[i] = 0.f; g_ssx[i] = 0.f; g_ssy[i] = 0.f; g_ssz[i] = 0.f;
    }
    if (i < MAXB * KMAX) {
        g_uniq[i] = EMPTYK;
        g_cnt[i] = 0.f; g_fsum[i] = 0.f; g_own[i] = 0.f; g_hub[i] = 0.f;
        g_h4[i]  = make_float4(0.f, 0.f, 0.f, 1.f);
        g_mrw[i] = make_float4(0.f, 0.f, 0.f, 0.f);
    }
    if (i < MAXB) g_kreal[i] = 0;
}

// Fused collect + per-segment accumulation, per-block shared hash.
__global__ void __launch_bounds__(256) k_collect(const float* __restrict__ pred,
                                                 const float* __restrict__ tgt, int P) {
    int b = blockIdx.y;
    __shared__ unsigned skey[HASHN];
    __shared__ float scnt[HASHN], ssx[HASHN], ssy[HASHN], ssz[HASHN];
    int tid = threadIdx.x;
    skey[tid] = EMPTYK;
    scnt[tid] = 0.f; ssx[tid] = 0.f; ssy[tid] = 0.f; ssz[tid] = 0.f;
    __syncthreads();

    const float* t  = tgt  + (size_t)b * 3 * P;
    const float* pr = pred + (size_t)b * 3 * P;
    int nvec = P >> 2;
    const float4* tx4 = (const float4*)(t);
    const float4* ty4 = (const float4*)(t + P);
    const float4* tz4 = (const float4*)(t + 2 * P);
    const float4* px4 = (const float4*)(pr);
    const float4* py4 = (const float4*)(pr + P);
    const float4* pz4 = (const float4*)(pr + 2 * P);
    int start  = blockIdx.x * blockDim.x + tid;
    int stride = gridDim.x * blockDim.x;

    for (int v = start; v < nvec; v += stride) {
        float4 r = tx4[v], g = ty4[v], bl = tz4[v];
        float4 x = px4[v], y = py4[v], z = pz4[v];
        unsigned keys[4] = { make_key(r.x, g.x, bl.x), make_key(r.y, g.y, bl.y),
                             make_key(r.z, g.z, bl.z), make_key(r.w, g.w, bl.w) };
        float pxs[4] = { x.x, x.y, x.z, x.w };
        float pys[4] = { y.x, y.y, y.z, y.w };
        float pzs[4] = { z.x, z.y, z.z, z.w };
        #pragma unroll
        for (int i = 0; i < 4; i++) {
            unsigned key = keys[i];
            unsigned slot = (key * 2654435761u) >> 24;
            #pragma unroll 1
            for (;;) {
                unsigned cur = *(volatile unsigned*)&skey[slot];
                if (cur == key) break;
                if (cur == EMPTYK) {
                    unsigned old = atomicCAS(&skey[slot], EMPTYK, key);
                    if (old == EMPTYK || old == key) break;
                }
                slot = (slot + 1) & (HASHN - 1);
            }
            atomicAdd(&scnt[slot], 1.0f);
            atomicAdd(&ssx[slot], pxs[i]);
            atomicAdd(&ssy[slot], pys[i]);
            atomicAdd(&ssz[slot], pzs[i]);
        }
    }
    if (blockIdx.x == 0) {  // scalar tail
        for (int p = (nvec << 2) + tid; p < P; p += blockDim.x) {
            unsigned key = make_key(t[p], t[P + p], t[2 * P + p]);
            unsigned slot = (key * 2654435761u) >> 24;
            #pragma unroll 1
            for (;;) {
                unsigned cur = *(volatile unsigned*)&skey[slot];
                if (cur == key) break;
                if (cur == EMPTYK) {
                    unsigned old = atomicCAS(&skey[slot], EMPTYK, key);
                    if (old == EMPTYK || old == key) break;
                }
                slot = (slot + 1) & (HASHN - 1);
            }
            atomicAdd(&scnt[slot], 1.0f);
            atomicAdd(&ssx[slot], pr[p]);
            atomicAdd(&ssy[slot], pr[P + p]);
            atomicAdd(&ssz[slot], pr[2 * P + p]);
        }
    }
    __syncthreads();

    unsigned mk = skey[tid];
    if (mk != EMPTYK) {
        unsigned gs = (mk * 2654435761u) >> 24;
        #pragma unroll 1
        for (;;) {
            unsigned cur = __ldcg(&g_hash[b * HASHN + gs]);
            if (cur == mk) break;
            if (cur == EMPTYK) {
                unsigned old = atomicCAS(&g_hash[b * HASHN + gs], EMPTYK, mk);
                if (old == EMPTYK || old == mk) break;
            }
            gs = (gs + 1) & (HASHN - 1);
        }
        atomicAdd(&g_scnt[b * HASHN + gs], scnt[tid]);
        atomicAdd(&g_ssx [b * HASHN + gs], ssx[tid]);
        atomicAdd(&g_ssy [b * HASHN + gs], ssy[tid]);
        atomicAdd(&g_ssz [b * HASHN + gs], ssz[tid]);
    }
}

// Rank unique keys; produce means / h4 tables in rank order.
__global__ void k_rank() {
    int b = blockIdx.x;
    __shared__ unsigned keys[HASHN];
    __shared__ int scount;
    int tid = threadIdx.x;
    keys[tid] = g_hash[b * HASHN + tid];
    if (tid == 0) scount = 0;
    __syncthreads();
    unsigned mk = keys[tid];
    if (mk != EMPTYK) {
        int rank = 0;
        #pragma unroll 8
        for (int i = 0; i < HASHN; i++) rank += (keys[i] < mk) ? 1 : 0;
        atomicAdd(&scount, 1);
        if (rank < KMAX) {
            float c = g_scnt[b * HASHN + tid];
            float n = fmaxf(c, 1.0f);
            float inv = 1.0f / n;
            float mx = g_ssx[b * HASHN + tid] * inv;
            float my = g_ssy[b * HASHN + tid] * inv;
            float mz = g_ssz[b * HASHN + tid] * inv;
            float m2 = mx * mx + my * my + mz * mz;
            g_uniq[b * KMAX + rank] = mk;
            g_cnt [b * KMAX + rank] = c;
            g_h4  [b * KMAX + rank] = make_float4(-2.f * mx, -2.f * my, -2.f * mz, m2 + 1.0f);
            g_mrw [b * KMAX + rank] = make_float4(mx, my, mz, (mk == 0u) ? 1.f : 0.f);
        }
    }
    __syncthreads();
    if (tid == 0) g_kreal[b] = min(scount, KMAX);
}

__device__ __forceinline__ int seg_search(const unsigned* us, unsigned key) {
    int pos = 0;
    #pragma unroll
    for (int st = 32; st >= 1; st >>= 1)
        if (us[pos + st] <= key) pos += st;
    return pos;
}

// ---- part A: per-pixel segment id, huber, own-f ----
__global__ void __launch_bounds__(256) k_own(const float* __restrict__ pred,
                                             const float* __restrict__ tgt, int P) {
    int b = blockIdx.y;
    __shared__ unsigned us[KMAX];
    __shared__ float4 ms[KMAX];
    __shared__ float hub_sh[KMAX], own_sh[KMAX];
    int tid = threadIdx.x;
    if (tid < KMAX) {
        us[tid] = g_uniq[b * KMAX + tid];
        ms[tid] = g_mrw[b * KMAX + tid];
        hub_sh[tid] = 0.f; own_sh[tid] = 0.f;
    }
    __syncthreads();
    const float* t  = tgt  + (size_t)b * 3 * P;
    const float* pr = pred + (size_t)b * 3 * P;
    int nvec = P >> 2;
    const float4* tx4 = (const float4*)(t);
    const float4* ty4 = (const float4*)(t + P);
    const float4* tz4 = (const float4*)(t + 2 * P);
    const float4* px4 = (const float4*)(pr);
    const float4* py4 = (const float4*)(pr + P);
    const float4* pz4 = (const float4*)(pr + 2 * P);
    int start  = blockIdx.x * blockDim.x + tid;
    int stride = gridDim.x * blockDim.x;

    for (int v = start; v < nvec; v += stride) {
        float4 r = tx4[v], g = ty4[v], bl = tz4[v];
        float4 x = px4[v], y = py4[v], z = pz4[v];
        unsigned keys[4] = { make_key(r.x, g.x, bl.x), make_key(r.y, g.y, bl.y),
                             make_key(r.z, g.z, bl.z), make_key(r.w, g.w, bl.w) };
        float pxs[4] = { x.x, x.y, x.z, x.w };
        float pys[4] = { y.x, y.y, y.z, y.w };
        float pzs[4] = { z.x, z.y, z.z, z.w };
        #pragma unroll
        for (int i = 0; i < 4; i++) {
            int pos = seg_search(us, keys[i]);
            float4 m = ms[pos];
            float dx = pxs[i] - m.x, dy = pys[i] - m.y, dz = pzs[i] - m.z;
            float d = fmaf(dx, dx, fmaf(dy, dy, dz * dz));
            atomicAdd(&own_sh[pos], fast_rcp(1.0f + d));
            bool bg = (m.w != 0.f);
            float ex = bg ? pxs[i] : dx;
            float ey = bg ? pys[i] : dy;
            float ez = bg ? pzs[i] : dz;
            float hh = 0.f, a;
            a = fabsf(ex); hh += (a < 1.f) ? 0.5f * ex * ex : a - 0.5f;
            a = fabsf(ey); hh += (a < 1.f) ? 0.5f * ey * ey : a - 0.5f;
            a = fabsf(ez); hh += (a < 1.f) ? 0.5f * ez * ez : a - 0.5f;
            atomicAdd(&hub_sh[pos], hh);
        }
    }
    if (blockIdx.x == 0) {  // scalar tail
        for (int p = (nvec << 2) + tid; p < P; p += blockDim.x) {
            float px = pr[p], py = pr[P + p], pz = pr[2 * P + p];
            unsigned key = make_key(t[p], t[P + p], t[2 * P + p]);
            int pos = seg_search(us, key);
            float4 m = ms[pos];
            float dx = px - m.x, dy = py - m.y, dz = pz - m.z;
            float d = fmaf(dx, dx, fmaf(dy, dy, dz * dz));
            atomicAdd(&own_sh[pos], fast_rcp(1.0f + d));
            bool bg = (m.w != 0.f);
            float ex = bg ? px : dx, ey = bg ? py : dy, ez = bg ? pz : dz;
            float hh = 0.f, a;
            a = fabsf(ex); hh += (a < 1.f) ? 0.5f * ex * ex : a - 0.5f;
            a = fabsf(ey); hh += (a < 1.f) ? 0.5f * ey * ey : a - 0.5f;
            a = fabsf(ez); hh += (a < 1.f) ? 0.5f * ez * ez : a - 0.5f;
            atomicAdd(&hub_sh[pos], hh);
        }
    }
    __syncthreads();
    if (tid < KMAX) {
        if (hub_sh[tid] != 0.f) atomicAdd(&g_hub[b * KMAX + tid], hub_sh[tid]);
        if (own_sh[tid] != 0.f) atomicAdd(&g_own[b * KMAX + tid], own_sh[tid]);
    }
}

// ---- part B: dense f-sum, packed f32x2 + magic reciprocal ----
__global__ void __launch_bounds__(256, 2) k_sep(const float* __restrict__ pred, int P) {
    int b = blockIdx.y;
    int c0 = blockIdx.z * CH;
    int Kr = g_kreal[b];
    if (c0 >= Kr) return;
    int kl = min(CH, Kr - c0);

    __shared__ float fs_sh[CH];
    int tid = threadIdx.x;
    if (tid < CH) fs_sh[tid] = 0.f;
    __syncthreads();

    // pre-pack per-k coefficients into broadcast f32x2 pairs (registers)
    ull hx[CH], hy[CH], hz[CH], hw[CH];
    #pragma unroll
    for (int j = 0; j < CH; j++) {
        float4 h = (j < kl) ? g_h4[b * KMAX + c0 + j] : make_float4(0.f, 0.f, 0.f, 3.0e8f);
        hx[j] = pk2(h.x, h.x); hy[j] = pk2(h.y, h.y);
        hz[j] = pk2(h.z, h.z); hw[j] = pk2(h.w, h.w);
    }
    ull acc[CH];
    #pragma unroll
    for (int j = 0; j < CH; j++) acc[j] = 0ull;  // (+0.f, +0.f)

    const float* pr = pred + (size_t)b * 3 * P;
    int nvec2 = P >> 1;
    const ull* px2 = (const ull*)(pr);
    const ull* py2 = (const ull*)(pr + P);
    const ull* pz2 = (const ull*)(pr + 2 * P);
    int start  = blockIdx.x * blockDim.x + tid;
    int stride = gridDim.x * blockDim.x;

    for (int v = start; v < nvec2; v += stride) {
        ull x2 = px2[v], y2 = py2[v], z2 = pz2[v];
        ull cw2 = fma2_(z2, z2, fma2_(y2, y2, mul2_(x2, x2)));  // |p|^2 (the +1 lives in hw)
        #pragma unroll
        for (int j = 0; j < CH; j++) {
            ull tj = add2_(cw2, hw[j]);
            tj = fma2_(x2, hx[j], tj);
            tj = fma2_(y2, hy[j], tj);
            tj = fma2_(z2, hz[j], tj);      // = 1 + d for both lanes (>= ~0.9 always)
            float t0, t1;
            upk2(tj, t0, t1);
            acc[j] = add2_(acc[j], pk2(magic_rcp(t0), magic_rcp(t1)));
        }
    }
    // odd-P scalar tail (exact rcp; at most 1 pixel)
    if (blockIdx.x == 0 && tid == 0) {
        for (int p = (nvec2 << 1); p < P; p++) {
            float px = pr[p], py = pr[P + p], pz = pr[2 * P + p];
            float cw = fmaf(px, px, fmaf(py, py, pz * pz));
            for (int j = 0; j < kl; j++) {
                float t0, t1, hxs, hys, hzs, hws;
                upk2(hx[j], hxs, t1); upk2(hy[j], hys, t1);
                upk2(hz[j], hzs, t1); upk2(hw[j], hws, t1);
                float tt = fmaf(px, hxs, cw + hws);
                tt = fmaf(py, hys, tt);
                tt = fmaf(pz, hzs, tt);
                atomicAdd(&fs_sh[j], fast_rcp(fmaxf(tt, 1.0f)));
            }
        }
    }
    // reduce: lanes -> warp -> shared -> global
    #pragma unroll
    for (int j = 0; j < CH; j++) {
        float lo, hi;
        upk2(acc[j], lo, hi);
        float val = lo + hi;
        #pragma unroll
        for (int off = 16; off >= 1; off >>= 1)
            val += __shfl_xor_sync(0xFFFFFFFFu, val, off);
        if ((tid & 31) == 0) atomicAdd(&fs_sh[j], val);
    }
    __syncthreads();
    if (tid < kl) atomicAdd(&g_fsum[b * KMAX + c0 + tid], fs_sh[tid]);
}

__global__ void k_final(float* out, const void* nbg_raw, int B, int P) {
    int tid = threadIdx.x;           // B * KMAX threads
    int b = tid / KMAX, k = tid % KMAX;
    __shared__ float s_ct[MAXB], s_hub[MAXB], s_sep[MAXB], s_pair[MAXB];
    __shared__ float4 me_sh[MAXB * KMAX];
    __shared__ unsigned char cnted_sh[MAXB * KMAX];
    if (tid < MAXB) { s_ct[tid] = 0.f; s_hub[tid] = 0.f; s_sep[tid] = 0.f; s_pair[tid] = 0.f; }
    __syncthreads();

    bool counted = false;
    float4 me = make_float4(0.f, 0.f, 0.f, 0.f);
    if (b < B) {
        bool nb = get_nobg(nbg_raw, b);
        float c = g_cnt[b * KMAX + k];
        bool valid = (c > 0.f);
        float4 m = g_mrw[b * KMAX + k];
        bool isbg = (m.w != 0.f);
        counted = valid && (!isbg || !nb);
        if (!isbg) me = m;
        float n = fmaxf(c, 1.0f);
        if (counted) {
            atomicAdd(&s_ct[b], 1.f);
            atomicAdd(&s_hub[b], g_hub[b * KMAX + k] / (3.0f * n));
        }
        float n_out = (float)P - c;
        if (valid && !isbg && n_out > 0.f) {
            float sep_mean = LAMF * (g_fsum[b * KMAX + k] - g_own[b * KMAX + k]) / fmaxf(n_out, 1.0f);
            atomicAdd(&s_sep[b], (10.0f / sqrtf(n)) * sep_mean);
        }
    }
    me_sh[tid] = me;
    cnted_sh[tid] = counted ? 1 : 0;
    __syncthreads();

    if (b < B && counted) {
        float psum = 0.f;
        for (int k2 = 0; k2 < KMAX; k2++) {
            if (k2 == k || !cnted_sh[b * KMAX + k2]) continue;
            float4 o = me_sh[b * KMAX + k2];
            float dx = me.x - o.x, dy = me.y - o.y, dz = me.z - o.z;
            float sq = dx * dx + dy * dy + dz * dz;
            psum += LAMF / (sq + 1.0f);
        }
        atomicAdd(&s_pair[b], psum);
    }
    __syncthreads();
    if (tid == 0) {
        float tot = 0.f;
        for (int bb = 0; bb < B; bb++) {
            float ct = s_ct[bb];
            float pair_sum = s_pair[bb] * 0.5f;
            float n_pairs = ct * (ct - 1.0f) * 0.5f;
            float mean_sep = (ct > 1.0f) ? pair_sum / fmaxf(n_pairs, 1.0f) : 0.f;
            float loss = s_hub[bb] + s_sep[bb] + mean_sep;
            tot += loss / fmaxf(ct, 1.0f);
        }
        out[0] = tot / (float)B;
    }
}

// ---------------- launch ----------------
extern "C" void kernel_launch(void* const* d_in, const int* in_sizes, int n_in,
                              void* d_out, int out_size) {
    const float* pred = (const float*)d_in[0];
    const float* tgt  = (const float*)d_in[1];
    const void*  nbg  = d_in[2];
    int B = in_sizes[2];
    if (B > MAXB) B = MAXB;
    int P = in_sizes[0] / (3 * B);

    k_init<<<16, 256>>>();
    k_collect<<<dim3(256, B), 256>>>(pred, tgt, P);
    k_rank<<<B, HASHN>>>();
    k_own<<<dim3(148, B), 256>>>(pred, tgt, P);
    k_sep<<<dim3(37, B, NCHUNK), 256>>>(pred, P);
    k_final<<<1, B * KMAX>>>((float*)d_out, nbg, B, P);
}